// round 7
// baseline (speedup 1.0000x reference)
#include <cuda_runtime.h>
#include <cuda_fp16.h>
#include <math.h>
#include <stdint.h>

// GMM log-likelihood via mma.sync fp16 (sm_100 baseline PTX).
// out[b] = logsumexp_k( off_k - 0.5*||L_k x_b - m_k||^2 ), m_k = L_k mu_k.
// L lower-triangular: skip j-chunk > i-chunk MMA tiles AND their cp.async
// loads; i-chunks remapped per warp group {0,3,4,7}/{1,2,5,6} (balanced: 18
// k-chunks each). BR=64 rows/CTA, 256 threads, grid=1024 -> 2 CTAs/SM:
// kills wave quantization (3.5 vs 3.46 ideal) and cross-CTA-hides barriers.

#define NK 16
#define D 128
#define BR 64
#define THREADS 256
#define PASSES 16

#define XS_BYTES 272
#define SM_X 0                               // 64*272 = 17408
#define SM_L 17408
#define LBUF_BYTES (128 * XS_BYTES)          // 34816 (1 comp)
#define SM_M (SM_L + 2 * LBUF_BYTES)         // 87040 : float m[16][128]
#define SM_OFFS (SM_M + NK * D * 4)          // 95232 : float off[16]
#define SM_SRED (SM_OFFS + 64)               // 95296 : float [2][16][64]
#define SM_TOTAL (SM_SRED + 2 * NK * BR * 4) // 103488

__device__ __half g_Lh[NK * D * D];
__device__ float g_m[NK][D];
__device__ float g_off[NK];

// ---------------- fused prep: cvt fp16 + m_k + off_k ----------------
__global__ void gmm_prep_kernel(const float* __restrict__ means,
                                const float* __restrict__ prec,
                                const float* __restrict__ logw) {
    const int k = blockIdx.x;
    const int tid = threadIdx.x;
    const int wid = tid >> 5, lane = tid & 31;
    const float* Lk = prec + (size_t)k * D * D;

    __shared__ float mu_s[D];
    __shared__ float red[D];

    if (tid < D) mu_s[tid] = means[k * D + tid];
    if (tid < D) red[tid] = logf(Lk[tid * D + tid]);

    {
        const float4* s4 = (const float4*)Lk;
        uint2* d4 = (uint2*)(g_Lh + (size_t)k * D * D);
        #pragma unroll
        for (int i = 0; i < 16; ++i) {
            float4 v = s4[tid + i * 256];
            __half2 h0 = __floats2half2_rn(v.x, v.y);
            __half2 h1 = __floats2half2_rn(v.z, v.w);
            d4[tid + i * 256] = make_uint2(*(uint32_t*)&h0, *(uint32_t*)&h1);
        }
    }
    __syncthreads();

    for (int r = wid; r < D; r += 8) {
        float4 v = ((const float4*)(Lk + r * D))[lane];
        float4 m4 = *(const float4*)&mu_s[lane * 4];
        float d = v.x * m4.x + v.y * m4.y + v.z * m4.z + v.w * m4.w;
        #pragma unroll
        for (int o = 16; o > 0; o >>= 1) d += __shfl_xor_sync(~0u, d, o);
        if (lane == 0) g_m[k][r] = d;
    }

    for (int off = D / 2; off > 0; off >>= 1) {
        if (tid < off) red[tid] += red[tid + off];
        __syncthreads();
    }
    if (tid == 0)
        g_off[k] = logw[k] + red[0] - 64.0f * 1.8378770664093453f;
}

// ---------------- asm helpers ----------------
__device__ __forceinline__ uint32_t smem_u32(const void* p) {
    uint32_t a;
    asm("{ .reg .u64 t; cvta.to.shared.u64 t, %1; cvt.u32.u64 %0, t; }"
        : "=r"(a) : "l"(p));
    return a;
}
__device__ __forceinline__ void ldsm_x4(uint32_t& r0, uint32_t& r1,
                                        uint32_t& r2, uint32_t& r3,
                                        uint32_t addr) {
    asm volatile("ldmatrix.sync.aligned.m8n8.x4.shared.b16 {%0,%1,%2,%3}, [%4];"
                 : "=r"(r0), "=r"(r1), "=r"(r2), "=r"(r3) : "r"(addr));
}
__device__ __forceinline__ void mma_f16(float* c, uint32_t a0, uint32_t a1,
                                        uint32_t a2, uint32_t a3,
                                        uint32_t b0, uint32_t b1) {
    asm volatile(
        "mma.sync.aligned.m16n8k16.row.col.f32.f16.f16.f32 "
        "{%0,%1,%2,%3}, {%4,%5,%6,%7}, {%8,%9}, {%0,%1,%2,%3};"
        : "+f"(c[0]), "+f"(c[1]), "+f"(c[2]), "+f"(c[3])
        : "r"(a0), "r"(a1), "r"(a2), "r"(a3), "r"(b0), "r"(b1));
}
__device__ __forceinline__ void cp16(uint32_t dst, const void* src) {
    asm volatile("cp.async.cg.shared.global [%0], [%1], 16;"
                 :: "r"(dst), "l"(src) : "memory");
}

// Prefetch one component's L (fp16, lower triangle only) into smem buffer.
__device__ __forceinline__ void prefetch_L(uint32_t dstb, const char* src,
                                           int tid) {
    #pragma unroll
    for (int i = 0; i < 8; ++i) {
        int idx = tid + i * THREADS;
        int r = idx >> 4, c = idx & 15;          // c: 16B chunk (8 halves)
        if (c <= 2 * (r >> 4) + 1)               // lower-triangle chunks only
            cp16(dstb + r * XS_BYTES + c * 16, src + r * 256 + c * 16);
    }
    asm volatile("cp.async.commit_group;" ::: "memory");
}

// Triangular GEMM body: 16-row A tile, i-chunks I0..I3, keep s <= I.
template <int I0, int I1, int I2, int I3>
__device__ __forceinline__ void gemm_body(float acc[8][4], uint32_t aw,
                                          uint32_t lb) {
    constexpr int IM[4] = {I0, I1, I2, I3};
    constexpr int IMAX = (I3 > I0) ? I3 : I0;
    #pragma unroll
    for (int s = 0; s < 8; ++s) {
        if (s <= IMAX) {
            uint32_t a0, a1, a2, a3;
            ldsm_x4(a0, a1, a2, a3, aw + s * 32);
            #pragma unroll
            for (int nf2 = 0; nf2 < 4; ++nf2) {
                if (IM[nf2] >= s) {
                    uint32_t b0, b1, b2, b3;
                    ldsm_x4(b0, b1, b2, b3,
                            lb + IM[nf2] * (16 * XS_BYTES) + s * 32);
                    mma_f16(acc[2 * nf2], a0, a1, a2, a3, b0, b1);
                    mma_f16(acc[2 * nf2 + 1], a0, a1, a2, a3, b2, b3);
                }
            }
        }
    }
}

extern __shared__ char smem[];

__global__ __launch_bounds__(THREADS, 2)
void gmm_f16_kernel(const float* __restrict__ x, float* __restrict__ out) {
    const int tid = threadIdx.x;
    const int wid = tid >> 5;
    const int lane = tid & 31;
    const int wm = wid >> 1;          // 0..3 : 16-row M tile
    const int grp = wid & 1;          // i-chunk map selector
    const uint32_t sbase = smem_u32(smem);

    // --- prefetch L comp 0 ---
    prefetch_L(sbase + SM_L, (const char*)g_Lh, tid);

    // --- stage X (fp32 -> fp16): 64 rows ---
    {
        const float4* xg = (const float4*)(x + (size_t)blockIdx.x * BR * D);
        #pragma unroll
        for (int i = 0; i < 8; ++i) {
            int f = tid + i * THREADS;          // 0..2047
            float4 v = xg[f];
            __half2 h0 = __floats2half2_rn(v.x, v.y);
            __half2 h1 = __floats2half2_rn(v.z, v.w);
            int r = f >> 5, c4 = f & 31;
            *(uint2*)(smem + SM_X + r * XS_BYTES + c4 * 8) =
                make_uint2(*(uint32_t*)&h0, *(uint32_t*)&h1);
        }
    }
    // --- stage m, off ---
    {
        const float* gm = (const float*)g_m;
        #pragma unroll
        for (int i = 0; i < 8; ++i)
            ((float*)(smem + SM_M))[tid + i * THREADS] = gm[tid + i * THREADS];
        if (tid < NK) ((float*)(smem + SM_OFFS))[tid] = g_off[tid];
    }
    asm volatile("cp.async.wait_group 0;" ::: "memory");
    __syncthreads();

    const uint32_t a_lane = (uint32_t)((lane & 15) * XS_BYTES + (lane >> 4) * 16);
    const uint32_t b_lane = (uint32_t)(((lane >> 4) * 8 + (lane & 7)) * XS_BYTES +
                                       ((lane >> 3) & 1) * 16);
    const uint32_t aw = sbase + SM_X + wm * 16 * XS_BYTES + a_lane;

    const int imap4[4] = {grp ? 1 : 0, grp ? 2 : 3, grp ? 5 : 4, grp ? 6 : 7};

    for (int p = 0; p < PASSES; ++p) {
        if (p + 1 < PASSES)
            prefetch_L(sbase + SM_L + ((p + 1) & 1) * LBUF_BYTES,
                       (const char*)g_Lh + (size_t)(p + 1) * 32768, tid);

        const uint32_t lb = sbase + SM_L + (p & 1) * LBUF_BYTES + b_lane;

        float acc[8][4];
        #pragma unroll
        for (int nf = 0; nf < 8; ++nf)
            #pragma unroll
            for (int q = 0; q < 4; ++q) acc[nf][q] = 0.f;

        if (grp == 0) gemm_body<0, 3, 4, 7>(acc, aw, lb);
        else          gemm_body<1, 2, 5, 6>(acc, aw, lb);

        // --- epilogue: subtract m, square, quad-reduce, write-once SRED ---
        const float* m_comp = (const float*)(smem + SM_M) + p * D;
        float* sredw = (float*)(smem + SM_SRED) + (grp * NK + p) * BR;
        float rlo = 0.f, rhi = 0.f;
        #pragma unroll
        for (int nf = 0; nf < 8; ++nf) {
            int col = imap4[nf >> 1] * 16 + (nf & 1) * 8 + (lane & 3) * 2;
            float2 mv = *(const float2*)(m_comp + col);
            float v0 = acc[nf][0] - mv.x;
            float v1 = acc[nf][1] - mv.y;
            float v2 = acc[nf][2] - mv.x;
            float v3 = acc[nf][3] - mv.y;
            rlo = fmaf(v0, v0, fmaf(v1, v1, rlo));
            rhi = fmaf(v2, v2, fmaf(v3, v3, rhi));
        }
        rlo += __shfl_xor_sync(~0u, rlo, 1);
        rlo += __shfl_xor_sync(~0u, rlo, 2);
        rhi += __shfl_xor_sync(~0u, rhi, 1);
        rhi += __shfl_xor_sync(~0u, rhi, 2);
        if ((lane & 3) == 0) {
            int row = wm * 16 + (lane >> 2);
            sredw[row] = rlo;
            sredw[row + 8] = rhi;
        }

        if (p + 1 < PASSES) {
            asm volatile("cp.async.wait_group 0;" ::: "memory");
            __syncthreads();   // L[p+1] visible; buf (p+1)&1 reads done
        }
    }

    __syncthreads();   // all SRED writes visible

    if (tid < BR) {
        const float* sred = (const float*)(smem + SM_SRED);
        const float* offs = (const float*)(smem + SM_OFFS);
        float v[NK], mx = -INFINITY;
        #pragma unroll
        for (int k = 0; k < NK; ++k) {
            float s = sred[k * BR + tid] + sred[(NK + k) * BR + tid];
            v[k] = offs[k] - 0.5f * s;
            mx = fmaxf(mx, v[k]);
        }
        float e = 0.f;
        #pragma unroll
        for (int k = 0; k < NK; ++k) e += expf(v[k] - mx);
        out[blockIdx.x * BR + tid] = mx + logf(e);
    }
}

extern "C" void kernel_launch(void* const* d_in, const int* in_sizes, int n_in,
                              void* d_out, int out_size) {
    const float* x     = (const float*)d_in[0];
    const float* means = (const float*)d_in[1];
    const float* prec  = (const float*)d_in[2];
    const float* logw  = (const float*)d_in[3];
    float* out = (float*)d_out;

    const int B = in_sizes[0] / D;

    gmm_prep_kernel<<<NK, 256>>>(means, prec, logw);

    cudaFuncSetAttribute(gmm_f16_kernel,
                         cudaFuncAttributeMaxDynamicSharedMemorySize, SM_TOTAL);
    gmm_f16_kernel<<<B / BR, THREADS, SM_TOTAL>>>(x, out);
}

// round 9
// speedup vs baseline: 1.1300x; 1.1300x over previous
#include <cuda_runtime.h>
#include <cuda_fp16.h>
#include <math.h>
#include <stdint.h>

// GMM log-likelihood via mma.sync fp16 (sm_100 baseline PTX).
// out[b] = logsumexp_k( off_k - 0.5*||L_k x_b - m_k||^2 ), m_k = L_k mu_k.
// L lower-triangular: skip j-chunk > i-chunk MMA tiles AND their cp.async
// loads; i-chunk sets {0,3,4,7}/{1,2,5,6} per warp group (18 k-chunks each).
// BR=64, 256 threads, 2 CTAs/SM. A (X) fragments are REGISTER-RESIDENT:
// loaded once via 8 ldmatrix before the component loop, reused for all 16
// components -> only B ldmatrix remain in the hot loop.

#define NK 16
#define D 128
#define BR 64
#define THREADS 256
#define PASSES 16

#define XS_BYTES 272
#define SM_X 0                               // 64*272 = 17408
#define SM_L 17408
#define LBUF_BYTES (128 * XS_BYTES)          // 34816 (1 comp)
#define SM_M (SM_L + 2 * LBUF_BYTES)         // 87040 : float m[16][128]
#define SM_OFFS (SM_M + NK * D * 4)          // 95232 : float off[16]
#define SM_SRED (SM_OFFS + 64)               // 95296 : float [2][16][64]
#define SM_TOTAL (SM_SRED + 2 * NK * BR * 4) // 103488

__device__ __half g_Lh[NK * D * D];
__device__ float g_m[NK][D];
__device__ float g_off[NK];

// ---------------- fused prep: cvt fp16 + m_k + off_k ----------------
__global__ void gmm_prep_kernel(const float* __restrict__ means,
                                const float* __restrict__ prec,
                                const float* __restrict__ logw) {
    const int k = blockIdx.x;
    const int tid = threadIdx.x;
    const int wid = tid >> 5, lane = tid & 31;
    const float* Lk = prec + (size_t)k * D * D;

    __shared__ float mu_s[D];
    __shared__ float red[D];

    if (tid < D) mu_s[tid] = means[k * D + tid];
    if (tid < D) red[tid] = logf(Lk[tid * D + tid]);

    {
        const float4* s4 = (const float4*)Lk;
        uint2* d4 = (uint2*)(g_Lh + (size_t)k * D * D);
        #pragma unroll
        for (int i = 0; i < 16; ++i) {
            float4 v = s4[tid + i * 256];
            __half2 h0 = __floats2half2_rn(v.x, v.y);
            __half2 h1 = __floats2half2_rn(v.z, v.w);
            d4[tid + i * 256] = make_uint2(*(uint32_t*)&h0, *(uint32_t*)&h1);
        }
    }
    __syncthreads();

    for (int r = wid; r < D; r += 8) {
        float4 v = ((const float4*)(Lk + r * D))[lane];
        float4 m4 = *(const float4*)&mu_s[lane * 4];
        float d = v.x * m4.x + v.y * m4.y + v.z * m4.z + v.w * m4.w;
        #pragma unroll
        for (int o = 16; o > 0; o >>= 1) d += __shfl_xor_sync(~0u, d, o);
        if (lane == 0) g_m[k][r] = d;
    }

    for (int off = D / 2; off > 0; off >>= 1) {
        if (tid < off) red[tid] += red[tid + off];
        __syncthreads();
    }
    if (tid == 0)
        g_off[k] = logw[k] + red[0] - 64.0f * 1.8378770664093453f;
}

// ---------------- asm helpers ----------------
__device__ __forceinline__ uint32_t smem_u32(const void* p) {
    uint32_t a;
    asm("{ .reg .u64 t; cvta.to.shared.u64 t, %1; cvt.u32.u64 %0, t; }"
        : "=r"(a) : "l"(p));
    return a;
}
__device__ __forceinline__ void ldsm_x4(uint32_t& r0, uint32_t& r1,
                                        uint32_t& r2, uint32_t& r3,
                                        uint32_t addr) {
    asm volatile("ldmatrix.sync.aligned.m8n8.x4.shared.b16 {%0,%1,%2,%3}, [%4];"
                 : "=r"(r0), "=r"(r1), "=r"(r2), "=r"(r3) : "r"(addr));
}
__device__ __forceinline__ void mma_f16(float* c, uint32_t a0, uint32_t a1,
                                        uint32_t a2, uint32_t a3,
                                        uint32_t b0, uint32_t b1) {
    asm volatile(
        "mma.sync.aligned.m16n8k16.row.col.f32.f16.f16.f32 "
        "{%0,%1,%2,%3}, {%4,%5,%6,%7}, {%8,%9}, {%0,%1,%2,%3};"
        : "+f"(c[0]), "+f"(c[1]), "+f"(c[2]), "+f"(c[3])
        : "r"(a0), "r"(a1), "r"(a2), "r"(a3), "r"(b0), "r"(b1));
}
__device__ __forceinline__ void cp16(uint32_t dst, const void* src) {
    asm volatile("cp.async.cg.shared.global [%0], [%1], 16;"
                 :: "r"(dst), "l"(src) : "memory");
}

// Prefetch one component's L (fp16, lower triangle only) into smem buffer.
__device__ __forceinline__ void prefetch_L(uint32_t dstb, const char* src,
                                           int tid) {
    #pragma unroll
    for (int i = 0; i < 8; ++i) {
        int idx = tid + i * THREADS;
        int r = idx >> 4, c = idx & 15;          // c: 16B chunk (8 halves)
        if (c <= 2 * (r >> 4) + 1)               // lower-triangle chunks only
            cp16(dstb + r * XS_BYTES + c * 16, src + r * 256 + c * 16);
    }
    asm volatile("cp.async.commit_group;" ::: "memory");
}

// Triangular GEMM body with register-resident A fragments.
template <int I0, int I1, int I2, int I3>
__device__ __forceinline__ void gemm_body(float acc[8][4],
                                          const uint32_t afr[8][4],
                                          uint32_t lb) {
    constexpr int IM[4] = {I0, I1, I2, I3};
    constexpr int IMAX = (I3 > I0) ? I3 : I0;
    #pragma unroll
    for (int s = 0; s < 8; ++s) {
        if (s <= IMAX) {
            #pragma unroll
            for (int nf2 = 0; nf2 < 4; ++nf2) {
                if (IM[nf2] >= s) {
                    uint32_t b0, b1, b2, b3;
                    ldsm_x4(b0, b1, b2, b3,
                            lb + IM[nf2] * (16 * XS_BYTES) + s * 32);
                    mma_f16(acc[2 * nf2], afr[s][0], afr[s][1], afr[s][2],
                            afr[s][3], b0, b1);
                    mma_f16(acc[2 * nf2 + 1], afr[s][0], afr[s][1], afr[s][2],
                            afr[s][3], b2, b3);
                }
            }
        }
    }
}

extern __shared__ char smem[];

__global__ __launch_bounds__(THREADS, 2)
void gmm_f16_kernel(const float* __restrict__ x, float* __restrict__ out) {
    const int tid = threadIdx.x;
    const int wid = tid >> 5;
    const int lane = tid & 31;
    const int wm = wid >> 1;          // 0..3 : 16-row M tile
    const int grp = wid & 1;          // i-chunk map selector
    const uint32_t sbase = smem_u32(smem);

    // --- prefetch L comp 0 ---
    prefetch_L(sbase + SM_L, (const char*)g_Lh, tid);

    // --- stage X (fp32 -> fp16): 64 rows ---
    {
        const float4* xg = (const float4*)(x + (size_t)blockIdx.x * BR * D);
        #pragma unroll
        for (int i = 0; i < 8; ++i) {
            int f = tid + i * THREADS;
            float4 v = xg[f];
            __half2 h0 = __floats2half2_rn(v.x, v.y);
            __half2 h1 = __floats2half2_rn(v.z, v.w);
            int r = f >> 5, c4 = f & 31;
            *(uint2*)(smem + SM_X + r * XS_BYTES + c4 * 8) =
                make_uint2(*(uint32_t*)&h0, *(uint32_t*)&h1);
        }
    }
    // --- stage m, off ---
    {
        const float* gm = (const float*)g_m;
        #pragma unroll
        for (int i = 0; i < 8; ++i)
            ((float*)(smem + SM_M))[tid + i * THREADS] = gm[tid + i * THREADS];
        if (tid < NK) ((float*)(smem + SM_OFFS))[tid] = g_off[tid];
    }
    asm volatile("cp.async.wait_group 0;" ::: "memory");
    __syncthreads();

    const uint32_t a_lane = (uint32_t)((lane & 15) * XS_BYTES + (lane >> 4) * 16);
    const uint32_t b_lane = (uint32_t)(((lane >> 4) * 8 + (lane & 7)) * XS_BYTES +
                                       ((lane >> 3) & 1) * 16);
    const uint32_t aw = sbase + SM_X + wm * 16 * XS_BYTES + a_lane;

    // --- A fragments: load ONCE, resident for all 16 components ---
    uint32_t afr[8][4];
    #pragma unroll
    for (int s = 0; s < 8; ++s)
        ldsm_x4(afr[s][0], afr[s][1], afr[s][2], afr[s][3], aw + s * 32);

    const int imap4[4] = {grp ? 1 : 0, grp ? 2 : 3, grp ? 5 : 4, grp ? 6 : 7};
    // epilogue column byte-offsets (constant per warp)
    int colo[8];
    #pragma unroll
    for (int nf = 0; nf < 8; ++nf)
        colo[nf] = (imap4[nf >> 1] * 16 + (nf & 1) * 8 + (lane & 3) * 2) * 4;

    for (int p = 0; p < PASSES; ++p) {
        if (p + 1 < PASSES)
            prefetch_L(sbase + SM_L + ((p + 1) & 1) * LBUF_BYTES,
                       (const char*)g_Lh + (size_t)(p + 1) * 32768, tid);

        const uint32_t lb = sbase + SM_L + (p & 1) * LBUF_BYTES + b_lane;

        float acc[8][4];
        #pragma unroll
        for (int nf = 0; nf < 8; ++nf)
            #pragma unroll
            for (int q = 0; q < 4; ++q) acc[nf][q] = 0.f;

        if (grp == 0) gemm_body<0, 3, 4, 7>(acc, afr, lb);
        else          gemm_body<1, 2, 5, 6>(acc, afr, lb);

        // --- epilogue: subtract m, square, quad-reduce, write-once SRED ---
        const char* m_base = smem + SM_M + p * D * 4;
        float* sredw = (float*)(smem + SM_SRED) + (grp * NK + p) * BR;
        float rlo = 0.f, rhi = 0.f;
        #pragma unroll
        for (int nf = 0; nf < 8; ++nf) {
            float2 mv = *(const float2*)(m_base + colo[nf]);
            float v0 = acc[nf][0] - mv.x;
            float v1 = acc[nf][1] - mv.y;
            float v2 = acc[nf][2] - mv.x;
            float v3 = acc[nf][3] - mv.y;
            rlo = fmaf(v0, v0, fmaf(v1, v1, rlo));
            rhi = fmaf(v2, v2, fmaf(v3, v3, rhi));
        }
        rlo += __shfl_xor_sync(~0u, rlo, 1);
        rlo += __shfl_xor_sync(~0u, rlo, 2);
        rhi += __shfl_xor_sync(~0u, rhi, 1);
        rhi += __shfl_xor_sync(~0u, rhi, 2);
        if ((lane & 3) == 0) {
            int row = wm * 16 + (lane >> 2);
            sredw[row] = rlo;
            sredw[row + 8] = rhi;
        }

        if (p + 1 < PASSES) {
            asm volatile("cp.async.wait_group 0;" ::: "memory");
            __syncthreads();   // L[p+1] visible; buf (p+1)&1 reads done
        }
    }

    __syncthreads();   // all SRED writes visible

    if (tid < BR) {
        const float* sred = (const float*)(smem + SM_SRED);
        const float* offs = (const float*)(smem + SM_OFFS);
        float v[NK], mx = -INFINITY;
        #pragma unroll
        for (int k = 0; k < NK; ++k) {
            float s = sred[k * BR + tid] + sred[(NK + k) * BR + tid];
            v[k] = offs[k] - 0.5f * s;
            mx = fmaxf(mx, v[k]);
        }
        float e = 0.f;
        #pragma unroll
        for (int k = 0; k < NK; ++k) e += expf(v[k] - mx);
        out[blockIdx.x * BR + tid] = mx + logf(e);
    }
}

extern "C" void kernel_launch(void* const* d_in, const int* in_sizes, int n_in,
                              void* d_out, int out_size) {
    const float* x     = (const float*)d_in[0];
    const float* means = (const float*)d_in[1];
    const float* prec  = (const float*)d_in[2];
    const float* logw  = (const float*)d_in[3];
    float* out = (float*)d_out;

    const int B = in_sizes[0] / D;

    gmm_prep_kernel<<<NK, 256>>>(means, prec, logw);

    cudaFuncSetAttribute(gmm_f16_kernel,
                         cudaFuncAttributeMaxDynamicSharedMemorySize, SM_TOTAL);
    gmm_f16_kernel<<<B / BR, THREADS, SM_TOTAL>>>(x, out);
}

// round 11
// speedup vs baseline: 1.1571x; 1.0240x over previous
#include <cuda_runtime.h>
#include <cuda_fp16.h>
#include <math.h>
#include <stdint.h>

// GMM log-likelihood via mma.sync fp16 (sm_100 baseline PTX).
// out[b] = logsumexp_k( off_k - 0.5*||L_k x_b - m_k||^2 ), m_k = L_k mu_k.
// L lower-triangular: only j-chunk <= i-chunk tiles computed/loaded.
// 8 warps = 2 wm (32 rows) x 4 npair; warp npair owns i-chunks {n, 7-n}
// -> 9 k-chunks each (perfectly balanced) and each B ldmatrix feeds 4 MMAs
// (B-fragment smem traffic HALVED vs 16-row warps). A fragments register-
// resident across all 16 components. BR=64, 256 threads, 2 CTAs/SM.

#define NK 16
#define D 128
#define BR 64
#define THREADS 256
#define PASSES 16

#define XS_BYTES 272
#define SM_X 0                               // 64*272 = 17408
#define SM_L 17408
#define LBUF_BYTES (128 * XS_BYTES)          // 34816 (1 comp)
#define SM_M (SM_L + 2 * LBUF_BYTES)         // 87040 : float m[16][128]
#define SM_OFFS (SM_M + NK * D * 4)          // 95232 : float off[16]
#define SM_SRED (SM_OFFS + 64)               // 95296 : float [4][16][64]
#define SM_TOTAL (SM_SRED + 4 * NK * BR * 4) // 111680

__device__ __half g_Lh[NK * D * D];
__device__ float g_m[NK][D];
__device__ float g_off[NK];

// ---------------- fused prep: cvt fp16 + m_k + off_k ----------------
__global__ void gmm_prep_kernel(const float* __restrict__ means,
                                const float* __restrict__ prec,
                                const float* __restrict__ logw) {
    const int k = blockIdx.x;
    const int tid = threadIdx.x;
    const int wid = tid >> 5, lane = tid & 31;
    const float* Lk = prec + (size_t)k * D * D;

    __shared__ float mu_s[D];
    __shared__ float red[D];

    if (tid < D) mu_s[tid] = means[k * D + tid];
    if (tid < D) red[tid] = logf(Lk[tid * D + tid]);

    {
        const float4* s4 = (const float4*)Lk;
        uint2* d4 = (uint2*)(g_Lh + (size_t)k * D * D);
        #pragma unroll
        for (int i = 0; i < 16; ++i) {
            float4 v = s4[tid + i * 256];
            __half2 h0 = __floats2half2_rn(v.x, v.y);
            __half2 h1 = __floats2half2_rn(v.z, v.w);
            d4[tid + i * 256] = make_uint2(*(uint32_t*)&h0, *(uint32_t*)&h1);
        }
    }
    __syncthreads();

    for (int r = wid; r < D; r += 8) {
        float4 v = ((const float4*)(Lk + r * D))[lane];
        float4 m4 = *(const float4*)&mu_s[lane * 4];
        float d = v.x * m4.x + v.y * m4.y + v.z * m4.z + v.w * m4.w;
        #pragma unroll
        for (int o = 16; o > 0; o >>= 1) d += __shfl_xor_sync(~0u, d, o);
        if (lane == 0) g_m[k][r] = d;
    }

    for (int off = D / 2; off > 0; off >>= 1) {
        if (tid < off) red[tid] += red[tid + off];
        __syncthreads();
    }
    if (tid == 0)
        g_off[k] = logw[k] + red[0] - 64.0f * 1.8378770664093453f;
}

// ---------------- asm helpers ----------------
__device__ __forceinline__ uint32_t smem_u32(const void* p) {
    uint32_t a;
    asm("{ .reg .u64 t; cvta.to.shared.u64 t, %1; cvt.u32.u64 %0, t; }"
        : "=r"(a) : "l"(p));
    return a;
}
__device__ __forceinline__ void ldsm_x4(uint32_t& r0, uint32_t& r1,
                                        uint32_t& r2, uint32_t& r3,
                                        uint32_t addr) {
    asm volatile("ldmatrix.sync.aligned.m8n8.x4.shared.b16 {%0,%1,%2,%3}, [%4];"
                 : "=r"(r0), "=r"(r1), "=r"(r2), "=r"(r3) : "r"(addr));
}
__device__ __forceinline__ void mma_f16(float* c, uint32_t a0, uint32_t a1,
                                        uint32_t a2, uint32_t a3,
                                        uint32_t b0, uint32_t b1) {
    asm volatile(
        "mma.sync.aligned.m16n8k16.row.col.f32.f16.f16.f32 "
        "{%0,%1,%2,%3}, {%4,%5,%6,%7}, {%8,%9}, {%0,%1,%2,%3};"
        : "+f"(c[0]), "+f"(c[1]), "+f"(c[2]), "+f"(c[3])
        : "r"(a0), "r"(a1), "r"(a2), "r"(a3), "r"(b0), "r"(b1));
}
__device__ __forceinline__ void cp16(uint32_t dst, const void* src) {
    asm volatile("cp.async.cg.shared.global [%0], [%1], 16;"
                 :: "r"(dst), "l"(src) : "memory");
}

// Prefetch one component's L (fp16, lower triangle only) into smem buffer.
__device__ __forceinline__ void prefetch_L(uint32_t dstb, const char* src,
                                           int tid) {
    #pragma unroll
    for (int i = 0; i < 8; ++i) {
        int idx = tid + i * THREADS;
        int r = idx >> 4, c = idx & 15;          // c: 16B chunk (8 halves)
        if (c <= 2 * (r >> 4) + 1)               // lower-triangle chunks only
            cp16(dstb + r * XS_BYTES + c * 16, src + r * 256 + c * 16);
    }
    asm volatile("cp.async.commit_group;" ::: "memory");
}

// One i-chunk IC: k-chunks 0..IC, MMA into local acc (2 mf x 2 nf), then
// fused epilogue: subtract m, square, accumulate into rl/rh (acc dies here,
// keeping register pressure low despite 64 resident A-fragment regs).
template <int IC>
__device__ __forceinline__ void do_chunk(const uint32_t afr[2][8][4],
                                         uint32_t lb, const char* m_base,
                                         int lane, float rl[2], float rh[2]) {
    float acc[2][2][4];
    #pragma unroll
    for (int mf = 0; mf < 2; ++mf)
        #pragma unroll
        for (int nf = 0; nf < 2; ++nf)
            #pragma unroll
            for (int q = 0; q < 4; ++q) acc[mf][nf][q] = 0.f;

    #pragma unroll
    for (int s = 0; s <= IC; ++s) {
        uint32_t b0, b1, b2, b3;
        ldsm_x4(b0, b1, b2, b3, lb + IC * (16 * XS_BYTES) + s * 32);
        #pragma unroll
        for (int mf = 0; mf < 2; ++mf) {
            mma_f16(acc[mf][0], afr[mf][s][0], afr[mf][s][1], afr[mf][s][2],
                    afr[mf][s][3], b0, b1);
            mma_f16(acc[mf][1], afr[mf][s][0], afr[mf][s][1], afr[mf][s][2],
                    afr[mf][s][3], b2, b3);
        }
    }

    #pragma unroll
    for (int mf = 0; mf < 2; ++mf)
        #pragma unroll
        for (int nf = 0; nf < 2; ++nf) {
            float2 mv = *(const float2*)(m_base + (IC * 16 + nf * 8) * 4 +
                                         (lane & 3) * 8);
            float v0 = acc[mf][nf][0] - mv.x;
            float v1 = acc[mf][nf][1] - mv.y;
            float v2 = acc[mf][nf][2] - mv.x;
            float v3 = acc[mf][nf][3] - mv.y;
            rl[mf] = fmaf(v0, v0, fmaf(v1, v1, rl[mf]));
            rh[mf] = fmaf(v2, v2, fmaf(v3, v3, rh[mf]));
        }
}

extern __shared__ char smem[];

__global__ __launch_bounds__(THREADS, 2)
void gmm_f16_kernel(const float* __restrict__ x, float* __restrict__ out) {
    const int tid = threadIdx.x;
    const int wid = tid >> 5;
    const int lane = tid & 31;
    const int wm = wid >> 2;          // 0..1 : 32-row M tile
    const int npair = wid & 3;        // i-chunk pair {npair, 7-npair}
    const uint32_t sbase = smem_u32(smem);

    // --- prefetch L comp 0 ---
    prefetch_L(sbase + SM_L, (const char*)g_Lh, tid);

    // --- stage X (fp32 -> fp16): 64 rows ---
    {
        const float4* xg = (const float4*)(x + (size_t)blockIdx.x * BR * D);
        #pragma unroll
        for (int i = 0; i < 8; ++i) {
            int f = tid + i * THREADS;
            float4 v = xg[f];
            __half2 h0 = __floats2half2_rn(v.x, v.y);
            __half2 h1 = __floats2half2_rn(v.z, v.w);
            int r = f >> 5, c4 = f & 31;
            *(uint2*)(smem + SM_X + r * XS_BYTES + c4 * 8) =
                make_uint2(*(uint32_t*)&h0, *(uint32_t*)&h1);
        }
    }
    // --- stage m, off ---
    {
        const float* gm = (const float*)g_m;
        #pragma unroll
        for (int i = 0; i < 8; ++i)
            ((float*)(smem + SM_M))[tid + i * THREADS] = gm[tid + i * THREADS];
        if (tid < NK) ((float*)(smem + SM_OFFS))[tid] = g_off[tid];
    }
    asm volatile("cp.async.wait_group 0;" ::: "memory");
    __syncthreads();

    const uint32_t a_lane = (uint32_t)((lane & 15) * XS_BYTES + (lane >> 4) * 16);
    const uint32_t b_lane = (uint32_t)(((lane >> 4) * 8 + (lane & 7)) * XS_BYTES +
                                       ((lane >> 3) & 1) * 16);
    const uint32_t aw = sbase + SM_X + wm * 32 * XS_BYTES + a_lane;

    // --- A fragments: 32 rows x K=128, loaded ONCE for all 16 components ---
    uint32_t afr[2][8][4];
    #pragma unroll
    for (int mf = 0; mf < 2; ++mf)
        #pragma unroll
        for (int s = 0; s < 8; ++s)
            ldsm_x4(afr[mf][s][0], afr[mf][s][1], afr[mf][s][2], afr[mf][s][3],
                    aw + mf * (16 * XS_BYTES) + s * 32);

    for (int p = 0; p < PASSES; ++p) {
        if (p + 1 < PASSES)
            prefetch_L(sbase + SM_L + ((p + 1) & 1) * LBUF_BYTES,
                       (const char*)g_Lh + (size_t)(p + 1) * 32768, tid);

        const uint32_t lb = sbase + SM_L + (p & 1) * LBUF_BYTES + b_lane;
        const char* m_base = smem + SM_M + p * D * 4;

        float rl[2] = {0.f, 0.f}, rh[2] = {0.f, 0.f};
        switch (npair) {
            case 0: do_chunk<7>(afr, lb, m_base, lane, rl, rh);
                    do_chunk<0>(afr, lb, m_base, lane, rl, rh); break;
            case 1: do_chunk<6>(afr, lb, m_base, lane, rl, rh);
                    do_chunk<1>(afr, lb, m_base, lane, rl, rh); break;
            case 2: do_chunk<5>(afr, lb, m_base, lane, rl, rh);
                    do_chunk<2>(afr, lb, m_base, lane, rl, rh); break;
            default: do_chunk<4>(afr, lb, m_base, lane, rl, rh);
                     do_chunk<3>(afr, lb, m_base, lane, rl, rh); break;
        }

        // --- quad-reduce and write-once SRED[npair][p][row] ---
        float* sredw = (float*)(smem + SM_SRED) + (npair * NK + p) * BR;
        #pragma unroll
        for (int mf = 0; mf < 2; ++mf) {
            float lo = rl[mf], hi = rh[mf];
            lo += __shfl_xor_sync(~0u, lo, 1);
            lo += __shfl_xor_sync(~0u, lo, 2);
            hi += __shfl_xor_sync(~0u, hi, 1);
            hi += __shfl_xor_sync(~0u, hi, 2);
            if ((lane & 3) == 0) {
                int row = wm * 32 + mf * 16 + (lane >> 2);
                sredw[row] = lo;
                sredw[row + 8] = hi;
            }
        }

        if (p + 1 < PASSES) {
            asm volatile("cp.async.wait_group 0;" ::: "memory");
            __syncthreads();   // L[p+1] visible; buf (p+1)&1 reads done
        }
    }

    __syncthreads();   // all SRED writes visible

    if (tid < BR) {
        const float* sred = (const float*)(smem + SM_SRED);
        const float* offs = (const float*)(smem + SM_OFFS);
        float v[NK], mx = -INFINITY;
        #pragma unroll
        for (int k = 0; k < NK; ++k) {
            float s = sred[k * BR + tid] + sred[(NK + k) * BR + tid] +
                      sred[(2 * NK + k) * BR + tid] +
                      sred[(3 * NK + k) * BR + tid];
            v[k] = offs[k] - 0.5f * s;
            mx = fmaxf(mx, v[k]);
        }
        float e = 0.f;
        #pragma unroll
        for (int k = 0; k < NK; ++k) e += expf(v[k] - mx);
        out[blockIdx.x * BR + tid] = mx + logf(e);
    }
}

extern "C" void kernel_launch(void* const* d_in, const int* in_sizes, int n_in,
                              void* d_out, int out_size) {
    const float* x     = (const float*)d_in[0];
    const float* means = (const float*)d_in[1];
    const float* prec  = (const float*)d_in[2];
    const float* logw  = (const float*)d_in[3];
    float* out = (float*)d_out;

    const int B = in_sizes[0] / D;

    gmm_prep_kernel<<<NK, 256>>>(means, prec, logw);

    cudaFuncSetAttribute(gmm_f16_kernel,
                         cudaFuncAttributeMaxDynamicSharedMemorySize, SM_TOTAL);
    gmm_f16_kernel<<<B / BR, THREADS, SM_TOTAL>>>(x, out);
}